// round 2
// baseline (speedup 1.0000x reference)
#include <cuda_runtime.h>
#include <mma.h>
#include <math.h>

using namespace nvcuda;

#define DIM   1024
#define SEG   1024
#define NQ    512      // dilated rows per segment
#define NPROB 32       // 4 batches * 8 segments
static constexpr float SCALE = 0.03125f;  // 1/sqrt(1024)

// 32 MB scratch for softmax probabilities (fp32 to preserve accuracy)
__device__ float g_P[(size_t)NPROB * NQ * NQ];

// ---------------------------------------------------------------------------
// Kernel 1: per block = one 32-query tile of one problem, full 512 keys.
// S = (Q * scale) K^T via wmma tf32, fused row softmax, P -> g_P (fp32).
// ---------------------------------------------------------------------------
#define K1_BM  32
#define K1_LDQ 40
#define K1_LDK 40
#define K1_LDS 520
#define K1_SMEM_FLOATS (K1_BM * K1_LDQ + 512 * K1_LDK)  // 21760 floats = 87040 B

__global__ void k1_scores(const float* __restrict__ x) {
    extern __shared__ float sm1[];
    float* sQ = sm1;                        // [32][40]
    float* sK = sm1 + K1_BM * K1_LDQ;       // [512][40]
    float* sS = sm1;                        // [32][520]  (reuse after GEMM)

    const int qt = blockIdx.x;              // 0..15
    const int p  = blockIdx.y;              // 0..31
    const int b  = p >> 3, s = p & 7;
    const int q0 = qt * K1_BM;
    const int tid  = threadIdx.x;
    const int wid  = tid >> 5, lane = tid & 31;
    const int warp_m = wid >> 2;            // 0..1  (16 rows each)
    const int warp_n = wid & 3;             // 0..3  (128 cols each)

    const long base = ((long)b * 8192 + (long)s * SEG) * DIM;

    wmma::fragment<wmma::accumulator, 16, 16, 8, float> acc[8];
    #pragma unroll
    for (int i = 0; i < 8; i++) wmma::fill_fragment(acc[i], 0.0f);

    for (int kc = 0; kc < 32; kc++) {       // 1024 / 32
        const int k0 = kc * 32;
        // Q tile [32][32], pre-scaled
        {
            const int row = tid >> 3, f4 = tid & 7;
            float4 v = *reinterpret_cast<const float4*>(
                x + base + (long)(2 * (q0 + row)) * DIM + k0 + f4 * 4);
            v.x *= SCALE; v.y *= SCALE; v.z *= SCALE; v.w *= SCALE;
            *reinterpret_cast<float4*>(sQ + row * K1_LDQ + f4 * 4) = v;
        }
        // K tile [512][32]
        {
            const int r0 = tid >> 3, f4 = tid & 7;
            #pragma unroll
            for (int i = 0; i < 16; i++) {
                const int r = r0 + i * 32;
                float4 v = *reinterpret_cast<const float4*>(
                    x + base + (long)(2 * r) * DIM + k0 + f4 * 4);
                *reinterpret_cast<float4*>(sK + r * K1_LDK + f4 * 4) = v;
            }
        }
        __syncthreads();
        #pragma unroll
        for (int kk = 0; kk < 4; kk++) {
            wmma::fragment<wmma::matrix_a, 16, 16, 8, wmma::precision::tf32,
                           wmma::row_major> a;
            wmma::load_matrix_sync(a, sQ + warp_m * 16 * K1_LDQ + kk * 8, K1_LDQ);
            #pragma unroll
            for (int t = 0; t < a.num_elements; t++)
                a.x[t] = wmma::__float_to_tf32(a.x[t]);
            #pragma unroll
            for (int nf = 0; nf < 8; nf++) {
                wmma::fragment<wmma::matrix_b, 16, 16, 8, wmma::precision::tf32,
                               wmma::col_major> bf;   // B = K^T: (kk,n) at sK[n*ld + kk]
                wmma::load_matrix_sync(
                    bf, sK + (warp_n * 128 + nf * 16) * K1_LDK + kk * 8, K1_LDK);
                #pragma unroll
                for (int t = 0; t < bf.num_elements; t++)
                    bf.x[t] = wmma::__float_to_tf32(bf.x[t]);
                wmma::mma_sync(acc[nf], a, bf, acc[nf]);
            }
        }
        __syncthreads();
    }

    // Dump S to smem for cross-warp softmax
    #pragma unroll
    for (int nf = 0; nf < 8; nf++)
        wmma::store_matrix_sync(sS + warp_m * 16 * K1_LDS + warp_n * 128 + nf * 16,
                                acc[nf], K1_LDS, wmma::mem_row_major);
    __syncthreads();

    // Softmax: 4 rows per warp
    #pragma unroll
    for (int r = 0; r < 4; r++) {
        const int row = wid * 4 + r;
        float mx = -1e30f;
        #pragma unroll
        for (int j = 0; j < 16; j++)
            mx = fmaxf(mx, sS[row * K1_LDS + lane + j * 32]);
        #pragma unroll
        for (int off = 16; off > 0; off >>= 1)
            mx = fmaxf(mx, __shfl_xor_sync(0xffffffffu, mx, off));
        float vals[16], sum = 0.f;
        #pragma unroll
        for (int j = 0; j < 16; j++) {
            const float v = __expf(sS[row * K1_LDS + lane + j * 32] - mx);
            vals[j] = v; sum += v;
        }
        #pragma unroll
        for (int off = 16; off > 0; off >>= 1)
            sum += __shfl_xor_sync(0xffffffffu, sum, off);
        const float inv = 1.f / sum;
        float* dst = g_P + ((long)p * NQ + (q0 + row)) * NQ;
        #pragma unroll
        for (int j = 0; j < 16; j++)
            dst[lane + j * 32] = vals[j] * inv;
    }
}

// ---------------------------------------------------------------------------
// Kernel 2: O = P @ V, 128x128 tiles per block, wmma tf32.
// ---------------------------------------------------------------------------
#define K2_BM  128
#define K2_BN  128
#define K2_LDP 40
#define K2_LDV 136

__global__ void k2_pv(const float* __restrict__ x, float* __restrict__ out) {
    __shared__ float sP[K2_BM * K2_LDP];   // [128][40]
    __shared__ float sV[32 * K2_LDV];      // [32][136]

    const int nt = blockIdx.x;             // 0..7
    const int mt = blockIdx.y;             // 0..3
    const int p  = blockIdx.z;             // 0..31
    const int b = p >> 3, s = p & 7;
    const int m0 = mt * K2_BM, n0 = nt * K2_BN;
    const int tid = threadIdx.x;
    const int wid = tid >> 5;
    const int warp_m = wid >> 1;           // 0..3  (32 rows each)
    const int warp_n = wid & 1;            // 0..1  (64 cols each)

    const long base = ((long)b * 8192 + (long)s * SEG) * DIM;

    wmma::fragment<wmma::accumulator, 16, 16, 8, float> acc[2][4];
    #pragma unroll
    for (int i = 0; i < 2; i++)
        #pragma unroll
        for (int j = 0; j < 4; j++) wmma::fill_fragment(acc[i][j], 0.0f);

    for (int kc = 0; kc < 16; kc++) {      // 512 / 32
        // P tile [128][32]
        {
            const int r0 = tid >> 3, f4 = tid & 7;
            #pragma unroll
            for (int i = 0; i < 4; i++) {
                const int r = r0 + i * 32;
                float4 v = *reinterpret_cast<const float4*>(
                    g_P + ((long)p * NQ + m0 + r) * NQ + kc * 32 + f4 * 4);
                *reinterpret_cast<float4*>(sP + r * K2_LDP + f4 * 4) = v;
            }
        }
        // V tile [32][128]
        {
            const int f4 = tid & 31, r0 = tid >> 5;
            #pragma unroll
            for (int i = 0; i < 4; i++) {
                const int r = r0 + i * 8;
                const int jk = kc * 32 + r;
                float4 v = *reinterpret_cast<const float4*>(
                    x + base + (long)(2 * jk) * DIM + n0 + f4 * 4);
                *reinterpret_cast<float4*>(sV + r * K2_LDV + f4 * 4) = v;
            }
        }
        __syncthreads();
        #pragma unroll
        for (int kk = 0; kk < 4; kk++) {
            wmma::fragment<wmma::matrix_a, 16, 16, 8, wmma::precision::tf32,
                           wmma::row_major> a[2];
            #pragma unroll
            for (int am = 0; am < 2; am++) {
                wmma::load_matrix_sync(
                    a[am], sP + (warp_m * 32 + am * 16) * K2_LDP + kk * 8, K2_LDP);
                #pragma unroll
                for (int t = 0; t < a[am].num_elements; t++)
                    a[am].x[t] = wmma::__float_to_tf32(a[am].x[t]);
            }
            #pragma unroll
            for (int bn = 0; bn < 4; bn++) {
                wmma::fragment<wmma::matrix_b, 16, 16, 8, wmma::precision::tf32,
                               wmma::row_major> bf;  // (kk,n) at sV[kk*ld + n]
                wmma::load_matrix_sync(
                    bf, sV + kk * 8 * K2_LDV + warp_n * 64 + bn * 16, K2_LDV);
                #pragma unroll
                for (int t = 0; t < bf.num_elements; t++)
                    bf.x[t] = wmma::__float_to_tf32(bf.x[t]);
                #pragma unroll
                for (int am = 0; am < 2; am++)
                    wmma::mma_sync(acc[am][bn], a[am], bf, acc[am][bn]);
            }
        }
        __syncthreads();
    }

    // Store directly to output
    #pragma unroll
    for (int am = 0; am < 2; am++)
        #pragma unroll
        for (int bn = 0; bn < 4; bn++) {
            float* dst = out
                + ((long)(b * 4096 + s * 512 + m0 + warp_m * 32 + am * 16)) * DIM
                + n0 + warp_n * 64 + bn * 16;
            wmma::store_matrix_sync(dst, acc[am][bn], DIM, wmma::mem_row_major);
        }
}

// ---------------------------------------------------------------------------
extern "C" void kernel_launch(void* const* d_in, const int* in_sizes, int n_in,
                              void* d_out, int out_size) {
    const float* x = (const float*)d_in[0];
    float* out = (float*)d_out;

    cudaFuncSetAttribute(k1_scores, cudaFuncAttributeMaxDynamicSharedMemorySize,
                         K1_SMEM_FLOATS * (int)sizeof(float));
    k1_scores<<<dim3(16, NPROB), 256, K1_SMEM_FLOATS * sizeof(float)>>>(x);
    k2_pv<<<dim3(8, 4, NPROB), 256>>>(x, out);
}